// round 1
// baseline (speedup 1.0000x reference)
#include <cuda_runtime.h>
#include <cuda_bf16.h>
#include <cstdint>

// GaussianKernelDensity: out[m] = coeff + logsumexp_n( -||x_m - X_n||^2 / (2 b^2) )
// M=4096, N=50000, D=64. Strategy:
//  1) pack x, X to bf16 (+ exact fp32 squared norms)
//  2) fused bf16 HMMA (mma.sync m16n8k16) GEMM with online base-2 logsumexp epilogue,
//     N split across CTAs into NSPLIT partials (max, sum) in device scratch
//  3) combine partials per row.

#define MM 4096
#define NN 50000
#define DD 64
#define NPAD 50176              // >= max tile end (multiple of 128, covers nend-1+128)
#define NSPLIT 24
#define CHUNK ((NN + NSPLIT - 1) / NSPLIT)   // 2084
#define MT 64
#define NT 128

// device scratch (no allocations allowed)
__device__ __nv_bfloat16 g_Xb[NPAD * DD];
__device__ float         g_X2[NPAD];
__device__ __nv_bfloat16 g_xb[MM * DD];
__device__ float         g_x2[MM];
__device__ float2        g_part[NSPLIT * MM];

__device__ __forceinline__ float ex2(float x) {
    float r;
    asm("ex2.approx.ftz.f32 %0, %1;" : "=f"(r) : "f"(x));
    return r;
}
__device__ __forceinline__ float neg_inf() { return __int_as_float(0xff800000); }

// ---------------- pack kernels ----------------
// 8 threads per row; each thread converts 8 floats -> 8 bf16 and partial sum of squares.
__global__ void prep_X_kernel(const float* __restrict__ src) {
    int t = blockIdx.x * blockDim.x + threadIdx.x;
    int row = t >> 3, l8 = t & 7;           // grid sized so no stragglers
    uint4 packed = make_uint4(0u, 0u, 0u, 0u);
    __nv_bfloat16* hp = reinterpret_cast<__nv_bfloat16*>(&packed);
    float ss = 0.f;
    if (row < NN) {
        const float4* s4 = reinterpret_cast<const float4*>(src + row * DD + l8 * 8);
        float4 a = s4[0], b = s4[1];
        ss = a.x*a.x + a.y*a.y + a.z*a.z + a.w*a.w
           + b.x*b.x + b.y*b.y + b.z*b.z + b.w*b.w;
        hp[0] = __float2bfloat16_rn(a.x); hp[1] = __float2bfloat16_rn(a.y);
        hp[2] = __float2bfloat16_rn(a.z); hp[3] = __float2bfloat16_rn(a.w);
        hp[4] = __float2bfloat16_rn(b.x); hp[5] = __float2bfloat16_rn(b.y);
        hp[6] = __float2bfloat16_rn(b.z); hp[7] = __float2bfloat16_rn(b.w);
    }
    *reinterpret_cast<uint4*>(&g_Xb[row * DD + l8 * 8]) = packed;
    ss += __shfl_xor_sync(0xffffffffu, ss, 1);
    ss += __shfl_xor_sync(0xffffffffu, ss, 2);
    ss += __shfl_xor_sync(0xffffffffu, ss, 4);
    if (l8 == 0) g_X2[row] = ss;
}

__global__ void prep_x_kernel(const float* __restrict__ src) {
    int t = blockIdx.x * blockDim.x + threadIdx.x;
    int row = t >> 3, l8 = t & 7;
    const float4* s4 = reinterpret_cast<const float4*>(src + row * DD + l8 * 8);
    float4 a = s4[0], b = s4[1];
    float ss = a.x*a.x + a.y*a.y + a.z*a.z + a.w*a.w
             + b.x*b.x + b.y*b.y + b.z*b.z + b.w*b.w;
    uint4 packed;
    __nv_bfloat16* hp = reinterpret_cast<__nv_bfloat16*>(&packed);
    hp[0] = __float2bfloat16_rn(a.x); hp[1] = __float2bfloat16_rn(a.y);
    hp[2] = __float2bfloat16_rn(a.z); hp[3] = __float2bfloat16_rn(a.w);
    hp[4] = __float2bfloat16_rn(b.x); hp[5] = __float2bfloat16_rn(b.y);
    hp[6] = __float2bfloat16_rn(b.z); hp[7] = __float2bfloat16_rn(b.w);
    *reinterpret_cast<uint4*>(&g_xb[row * DD + l8 * 8]) = packed;
    ss += __shfl_xor_sync(0xffffffffu, ss, 1);
    ss += __shfl_xor_sync(0xffffffffu, ss, 2);
    ss += __shfl_xor_sync(0xffffffffu, ss, 4);
    if (l8 == 0) g_x2[row] = ss;
}

// ---------------- main fused GEMM + online LSE ----------------
// CTA: 256 threads (8 warps, 2x4 over M x N), tile 64x128, K=64 fully in registers.
// Logits in base-2: l2 = cross*(2*log2e/(2b^2)) - x2*inv2 - X2*inv2, clamped <= 0.
__global__ __launch_bounds__(256) void kde_main(const float* __restrict__ bw) {
    __shared__ __nv_bfloat16 xs[MT][72];     // 72 = 64 + 8 pad (conflict-free)
    __shared__ __nv_bfloat16 Xsm[NT][72];
    __shared__ float ct[NT];
    __shared__ float red[4][MT][2];

    const int tid  = threadIdx.x;
    const int warp = tid >> 5;
    const int lane = tid & 31;
    const int g = lane >> 2;
    const int c = lane & 3;
    const int wm = warp >> 2;   // 0..1
    const int wn = warp & 3;    // 0..3

    const float b    = bw[0];
    const float inv2 = 1.4426950408889634f / (2.f * b * b);  // log2(e)/(2 b^2)
    const float inv4 = 2.f * inv2;

    const int m0     = blockIdx.x * MT;
    const int split  = blockIdx.y;
    const int nstart = split * CHUNK;
    const int nend   = min(nstart + CHUNK, NN);

    // x tile -> smem (64 rows x 64 bf16)
    {
        int row = tid >> 2, q = tid & 3;
        const uint4* s = reinterpret_cast<const uint4*>(g_xb + (m0 + row) * DD + q * 16);
        uint4* d = reinterpret_cast<uint4*>(&xs[row][q * 16]);
        d[0] = s[0];
        d[1] = s[1];
    }

    // per-thread row terms (4 rows per thread)
    float rterm[4];
    #pragma unroll
    for (int r = 0; r < 4; r++) {
        int rl = wm * 32 + (r >> 1) * 16 + (r & 1) * 8 + g;
        rterm[r] = -g_x2[m0 + rl] * inv2;
    }

    float mmax[4], ssum[4];
    #pragma unroll
    for (int r = 0; r < 4; r++) { mmax[r] = -1e30f; ssum[r] = 0.f; }

    for (int nb = nstart; nb < nend; nb += NT) {
        __syncthreads();
        // X tile -> smem (128 rows x 64 bf16)
        {
            int row = tid >> 1, h = tid & 1;
            const uint4* s = reinterpret_cast<const uint4*>(g_Xb + (nb + row) * DD + h * 32);
            uint4* d = reinterpret_cast<uint4*>(&Xsm[row][h * 32]);
            d[0] = s[0]; d[1] = s[1]; d[2] = s[2]; d[3] = s[3];
        }
        if (tid < NT) {
            int n = nb + tid;
            ct[tid] = (n < nend) ? (-g_X2[n] * inv2) : neg_inf();
        }
        __syncthreads();

        float acc[2][4][4];
        #pragma unroll
        for (int i = 0; i < 2; i++)
            #pragma unroll
            for (int j = 0; j < 4; j++)
                #pragma unroll
                for (int q = 0; q < 4; q++) acc[i][j][q] = 0.f;

        #pragma unroll
        for (int ks = 0; ks < 4; ks++) {
            const int kb = ks * 16;
            uint32_t a[2][4], bb[4][2];
            #pragma unroll
            for (int i = 0; i < 2; i++) {
                int rb = wm * 32 + i * 16 + g;
                a[i][0] = *reinterpret_cast<const uint32_t*>(&xs[rb    ][kb + 2 * c    ]);
                a[i][1] = *reinterpret_cast<const uint32_t*>(&xs[rb + 8][kb + 2 * c    ]);
                a[i][2] = *reinterpret_cast<const uint32_t*>(&xs[rb    ][kb + 2 * c + 8]);
                a[i][3] = *reinterpret_cast<const uint32_t*>(&xs[rb + 8][kb + 2 * c + 8]);
            }
            #pragma unroll
            for (int j = 0; j < 4; j++) {
                int nr = wn * 32 + j * 8 + g;
                bb[j][0] = *reinterpret_cast<const uint32_t*>(&Xsm[nr][kb + 2 * c    ]);
                bb[j][1] = *reinterpret_cast<const uint32_t*>(&Xsm[nr][kb + 2 * c + 8]);
            }
            #pragma unroll
            for (int i = 0; i < 2; i++)
                #pragma unroll
                for (int j = 0; j < 4; j++)
                    asm volatile(
                        "mma.sync.aligned.m16n8k16.row.col.f32.bf16.bf16.f32 "
                        "{%0,%1,%2,%3}, {%4,%5,%6,%7}, {%8,%9}, {%0,%1,%2,%3};"
                        : "+f"(acc[i][j][0]), "+f"(acc[i][j][1]),
                          "+f"(acc[i][j][2]), "+f"(acc[i][j][3])
                        : "r"(a[i][0]), "r"(a[i][1]), "r"(a[i][2]), "r"(a[i][3]),
                          "r"(bb[j][0]), "r"(bb[j][1]));
        }

        // epilogue: online base-2 LSE with tile-max skip
        float cc[8];
        #pragma unroll
        for (int j = 0; j < 4; j++) {
            cc[2 * j]     = ct[wn * 32 + j * 8 + 2 * c];
            cc[2 * j + 1] = ct[wn * 32 + j * 8 + 2 * c + 1];
        }
        #pragma unroll
        for (int r = 0; r < 4; r++) {
            const int i = r >> 1, hf = r & 1;
            float v[8];
            #pragma unroll
            for (int j = 0; j < 4; j++) {
                v[2 * j]     = fminf(fmaf(acc[i][j][hf * 2],     inv4, cc[2 * j])     + rterm[r], 0.f);
                v[2 * j + 1] = fminf(fmaf(acc[i][j][hf * 2 + 1], inv4, cc[2 * j + 1]) + rterm[r], 0.f);
            }
            float t01 = fmaxf(v[0], v[1]), t23 = fmaxf(v[2], v[3]);
            float t45 = fmaxf(v[4], v[5]), t67 = fmaxf(v[6], v[7]);
            float tmax = fmaxf(fmaxf(t01, t23), fmaxf(t45, t67));
            if (tmax > mmax[r] - 25.f) {   // skip: contribution < 8 * 2^-25
                float nm = fmaxf(mmax[r], tmax);
                float e = ex2(v[0] - nm) + ex2(v[1] - nm) + ex2(v[2] - nm) + ex2(v[3] - nm)
                        + ex2(v[4] - nm) + ex2(v[5] - nm) + ex2(v[6] - nm) + ex2(v[7] - nm);
                ssum[r] = fmaf(ssum[r], ex2(mmax[r] - nm), e);
                mmax[r] = nm;
            }
        }
    }

    // reduce across the quad (lanes sharing a row)
    #pragma unroll
    for (int r = 0; r < 4; r++) {
        #pragma unroll
        for (int off = 1; off <= 2; off <<= 1) {
            float om = __shfl_xor_sync(0xffffffffu, mmax[r], off);
            float os = __shfl_xor_sync(0xffffffffu, ssum[r], off);
            float nm = fmaxf(mmax[r], om);
            ssum[r] = ssum[r] * ex2(mmax[r] - nm) + os * ex2(om - nm);
            mmax[r] = nm;
        }
    }
    __syncthreads();
    if (c == 0) {
        #pragma unroll
        for (int r = 0; r < 4; r++) {
            int rl = wm * 32 + (r >> 1) * 16 + (r & 1) * 8 + g;
            red[wn][rl][0] = mmax[r];
            red[wn][rl][1] = ssum[r];
        }
    }
    __syncthreads();
    if (tid < MT) {
        float m = red[0][tid][0], s = red[0][tid][1];
        #pragma unroll
        for (int w = 1; w < 4; w++) {
            float om = red[w][tid][0], os = red[w][tid][1];
            float nm = fmaxf(m, om);
            s = s * ex2(m - nm) + os * ex2(om - nm);
            m = nm;
        }
        g_part[split * MM + m0 + tid] = make_float2(m, s);
    }
}

// ---------------- combine partials ----------------
__global__ void kde_combine(float* __restrict__ out) {
    int m = blockIdx.x * blockDim.x + threadIdx.x;
    if (m >= MM) return;
    float mx = -1e30f;
    #pragma unroll
    for (int s = 0; s < NSPLIT; s++) mx = fmaxf(mx, g_part[s * MM + m].x);
    float sum = 0.f;
    #pragma unroll
    for (int s = 0; s < NSPLIT; s++) {
        float2 p = g_part[s * MM + m];
        sum += p.y * ex2(p.x - mx);
    }
    // coeff = -ln(50000) - 32*ln(2*pi);  (base-2 max converted back with ln 2)
    const float coeff = -69.63184440950933f;
    out[m] = coeff + mx * 0.6931471805599453f + logf(sum);
}

extern "C" void kernel_launch(void* const* d_in, const int* in_sizes, int n_in,
                              void* d_out, int out_size) {
    const float* x  = (const float*)d_in[0];   // [4096, 64]
    const float* X  = (const float*)d_in[1];   // [50000, 64]
    const float* bw = (const float*)d_in[2];   // [1]

    prep_X_kernel<<<NPAD / 32, 256>>>(X);      // 50176/32 = 1568 blocks, exact
    prep_x_kernel<<<MM / 32, 256>>>(x);        // 128 blocks, exact

    dim3 grid(MM / MT, NSPLIT);                // (64, 24)
    kde_main<<<grid, 256>>>(bw);

    kde_combine<<<(MM + 255) / 256, 256>>>((float*)d_out);
}

// round 3
// speedup vs baseline: 1.3046x; 1.3046x over previous
#include <cuda_runtime.h>
#include <cuda_bf16.h>
#include <cstdint>

// GaussianKernelDensity: out[m] = coeff + logsumexp_n( -||x_m - X_n||^2 / (2 b^2) )
// M=4096, N=50000, D=64.
//  Launch 1: prep_all  — pack x,X to bf16; fold norms+bandwidth into per-row/col
//            base-2 constants (colc = -|X|^2*inv2, rowc = -|x|^2*inv2 + 38).
//  Launch 2: kde_main  — bf16 HMMA (mma.sync m16n8k16) with A-fragments held in
//            registers, B via ldmatrix from cp.async double-buffered smem, fused
//            fixed-offset exp2 epilogue (no max tracking, no MUFU; v clamped at
//            -170 so the int32 exponent splice can never wrap), per-split row
//            sums, tail-CTA merge writes the output (atomic counter per m-block).

#define MM 4096
#define NN 50000
#define DD 64
#define NPAD 50176
#define NSPLIT 23
#define CHUNK 2176              // 17 * 128
#define NTILES 17
#define MT 64
#define NT 128
#define MAGICF 12582912.0f      // 1.5 * 2^23

// device scratch
__device__ __nv_bfloat16 g_Xb[NPAD * DD];
__device__ float         g_CT[NPAD];       // -|X_n|^2 * inv2  (pad rows: -1000)
__device__ __nv_bfloat16 g_xb[MM * DD];
__device__ float         g_RT[MM];         // -|x_m|^2 * inv2 + 38
__device__ float         g_part[NSPLIT * MM];
__device__ int           g_cnt[MM / MT];

#define LDSM4(r0, r1, r2, r3, addr)                                              \
    asm volatile("ldmatrix.sync.aligned.m8n8.x4.shared.b16 {%0,%1,%2,%3}, [%4];" \
                 : "=r"(r0), "=r"(r1), "=r"(r2), "=r"(r3) : "r"(addr))

__device__ __forceinline__ void cp16(uint32_t dst, const void* src) {
    asm volatile("cp.async.cg.shared.global [%0], [%1], 16;" :: "r"(dst), "l"(src));
}
__device__ __forceinline__ uint32_t smem_u32(const void* p) {
    return (uint32_t)__cvta_generic_to_shared(p);
}

// ---------------- prep: pack + fold constants ----------------
__global__ void prep_all(const float* __restrict__ xin,
                         const float* __restrict__ Xin,
                         const float* __restrict__ bw) {
    const float b = bw[0];
    const float inv2 = 1.4426950408889634f / (2.f * b * b);   // log2e / (2 b^2)
    const int blk = blockIdx.x, tid = threadIdx.x;
    const int l8 = tid & 7;

    if (blk < NPAD / 32) {                       // X rows (incl. pad)
        int row = blk * 32 + (tid >> 3);
        uint4 packed = make_uint4(0u, 0u, 0u, 0u);
        __nv_bfloat16* hp = reinterpret_cast<__nv_bfloat16*>(&packed);
        float ss = 0.f;
        if (row < NN) {
            const float4* s4 = reinterpret_cast<const float4*>(Xin + row * DD + l8 * 8);
            float4 a = s4[0], d = s4[1];
            ss = a.x*a.x + a.y*a.y + a.z*a.z + a.w*a.w
               + d.x*d.x + d.y*d.y + d.z*d.z + d.w*d.w;
            hp[0] = __float2bfloat16_rn(a.x); hp[1] = __float2bfloat16_rn(a.y);
            hp[2] = __float2bfloat16_rn(a.z); hp[3] = __float2bfloat16_rn(a.w);
            hp[4] = __float2bfloat16_rn(d.x); hp[5] = __float2bfloat16_rn(d.y);
            hp[6] = __float2bfloat16_rn(d.z); hp[7] = __float2bfloat16_rn(d.w);
        }
        *reinterpret_cast<uint4*>(&g_Xb[row * DD + l8 * 8]) = packed;
        ss += __shfl_xor_sync(0xffffffffu, ss, 1);
        ss += __shfl_xor_sync(0xffffffffu, ss, 2);
        ss += __shfl_xor_sync(0xffffffffu, ss, 4);
        if (l8 == 0) g_CT[row] = (row < NN) ? (-ss * inv2) : -1000.f;
    } else {                                     // x rows
        int row = (blk - NPAD / 32) * 32 + (tid >> 3);
        const float4* s4 = reinterpret_cast<const float4*>(xin + row * DD + l8 * 8);
        float4 a = s4[0], d = s4[1];
        float ss = a.x*a.x + a.y*a.y + a.z*a.z + a.w*a.w
                 + d.x*d.x + d.y*d.y + d.z*d.z + d.w*d.w;
        uint4 packed;
        __nv_bfloat16* hp = reinterpret_cast<__nv_bfloat16*>(&packed);
        hp[0] = __float2bfloat16_rn(a.x); hp[1] = __float2bfloat16_rn(a.y);
        hp[2] = __float2bfloat16_rn(a.z); hp[3] = __float2bfloat16_rn(a.w);
        hp[4] = __float2bfloat16_rn(d.x); hp[5] = __float2bfloat16_rn(d.y);
        hp[6] = __float2bfloat16_rn(d.z); hp[7] = __float2bfloat16_rn(d.w);
        *reinterpret_cast<uint4*>(&g_xb[row * DD + l8 * 8]) = packed;
        ss += __shfl_xor_sync(0xffffffffu, ss, 1);
        ss += __shfl_xor_sync(0xffffffffu, ss, 2);
        ss += __shfl_xor_sync(0xffffffffu, ss, 4);
        if (l8 == 0) g_RT[row] = -ss * inv2 + 38.f;
    }
}

// ---------------- main: GEMM + fixed-offset exp2 sum ----------------
__global__ __launch_bounds__(256, 2) void kde_main(const float* __restrict__ bw,
                                                   float* __restrict__ out) {
    __shared__ __nv_bfloat16 xs[MT][72];          //  9216 B
    __shared__ __nv_bfloat16 Xd[2][NT][72];       // 36864 B
    __shared__ float ctile[2][NT];                //  1024 B
    __shared__ float red[4][MT];                  //  1024 B
    __shared__ int sdone;

    const int tid  = threadIdx.x;
    const int warp = tid >> 5;
    const int lane = tid & 31;
    const int g = lane >> 2;
    const int c = lane & 3;
    const int wm = warp >> 2;     // 0..1 (M)
    const int wn = warp & 3;      // 0..3 (N)

    const float b    = bw[0];
    const float inv4 = 1.4426950408889634f / (b * b);   // log2e / b^2

    const int m0    = blockIdx.x * MT;
    const int split = blockIdx.y;
    const int n0    = split * CHUNK;

    // ---- x tile -> smem ----
    {
        int row = tid >> 2, q = tid & 3;
        const uint4* s = reinterpret_cast<const uint4*>(g_xb + (m0 + row) * DD + q * 16);
        uint4 v0 = s[0], v1 = s[1];
        *reinterpret_cast<uint4*>(&xs[row][q * 16])     = v0;
        *reinterpret_cast<uint4*>(&xs[row][q * 16 + 8]) = v1;
    }

    // ---- prefetch tile 0 ----
    {
        const int nb = n0;
        #pragma unroll
        for (int k = 0; k < 4; k++) {
            int idx = tid + k * 256; int row = idx >> 3, ch = idx & 7;
            cp16(smem_u32(&Xd[0][row][ch * 8]), g_Xb + (nb + row) * DD + ch * 8);
        }
        if (tid < 32) cp16(smem_u32(&ctile[0][tid * 4]), g_CT + nb + tid * 4);
        asm volatile("cp.async.commit_group;");
    }
    __syncthreads();    // xs ready

    // ---- A fragments for the whole CTA lifetime (8 LDSM.x4 = 32 regs) ----
    const int lr = (lane & 7) + ((lane >> 3) & 1) * 8;
    const int lc = (lane >> 4) * 8;
    uint32_t afr[4][8];
    #pragma unroll
    for (int ks = 0; ks < 4; ks++)
        #pragma unroll
        for (int i = 0; i < 2; i++) {
            uint32_t a0, a1, a2, a3;
            uint32_t addr = smem_u32(&xs[wm * 32 + i * 16 + lr][ks * 16 + lc]);
            LDSM4(a0, a1, a2, a3, addr);
            afr[ks][i * 4 + 0] = a0; afr[ks][i * 4 + 1] = a1;
            afr[ks][i * 4 + 2] = a2; afr[ks][i * 4 + 3] = a3;
        }

    float rowc[4];
    #pragma unroll
    for (int r = 0; r < 4; r++) {
        int rl = wm * 32 + (r >> 1) * 16 + (r & 1) * 8 + g;
        rowc[r] = g_RT[m0 + rl];
    }
    float sum[4] = {0.f, 0.f, 0.f, 0.f};

    for (int it = 0; it < NTILES; it++) {
        const int st = it & 1;
        if (it + 1 < NTILES) {
            const int nb = n0 + (it + 1) * NT;
            #pragma unroll
            for (int k = 0; k < 4; k++) {
                int idx = tid + k * 256; int row = idx >> 3, ch = idx & 7;
                cp16(smem_u32(&Xd[st ^ 1][row][ch * 8]), g_Xb + (nb + row) * DD + ch * 8);
            }
            if (tid < 32) cp16(smem_u32(&ctile[st ^ 1][tid * 4]), g_CT + nb + tid * 4);
            asm volatile("cp.async.commit_group;");
            asm volatile("cp.async.wait_group 1;");
        } else {
            asm volatile("cp.async.wait_group 0;");
        }
        __syncthreads();

        float2 ct2[4];
        #pragma unroll
        for (int j = 0; j < 4; j++)
            ct2[j] = *reinterpret_cast<const float2*>(&ctile[st][wn * 32 + j * 8 + 2 * c]);

        float acc[2][4][4];
        #pragma unroll
        for (int i = 0; i < 2; i++)
            #pragma unroll
            for (int j = 0; j < 4; j++)
                #pragma unroll
                for (int q = 0; q < 4; q++) acc[i][j][q] = 0.f;

        #pragma unroll
        for (int ks = 0; ks < 4; ks++) {
            uint32_t bfr[2][4];
            #pragma unroll
            for (int jj = 0; jj < 2; jj++) {
                uint32_t addr = smem_u32(&Xd[st][wn * 32 + jj * 16 + lr][ks * 16 + lc]);
                LDSM4(bfr[jj][0], bfr[jj][1], bfr[jj][2], bfr[jj][3], addr);
            }
            #pragma unroll
            for (int i = 0; i < 2; i++)
                #pragma unroll
                for (int j = 0; j < 4; j++) {
                    const int jj = j >> 1, od = j & 1;
                    asm volatile(
                        "mma.sync.aligned.m16n8k16.row.col.f32.bf16.bf16.f32 "
                        "{%0,%1,%2,%3}, {%4,%5,%6,%7}, {%8,%9}, {%0,%1,%2,%3};"
                        : "+f"(acc[i][j][0]), "+f"(acc[i][j][1]),
                          "+f"(acc[i][j][2]), "+f"(acc[i][j][3])
                        : "r"(afr[ks][i * 4 + 0]), "r"(afr[ks][i * 4 + 1]),
                          "r"(afr[ks][i * 4 + 2]), "r"(afr[ks][i * 4 + 3]),
                          "r"(bfr[jj][od]), "r"(bfr[jj][2 + od]));
                }
        }

        // epilogue: e = 2^v, v = acc*inv4 + colc + rowc (offset +38 folded in rowc).
        // Fixed-lat exp2: clamp v >= -170 (int splice cannot wrap; 2^-170 region
        // flushes to 0 via the integer max), round via magic const, deg-2 poly on
        // f in [-0.5,0.5], exponent added in int domain.
        #pragma unroll
        for (int r = 0; r < 4; r++) {
            const int i = r >> 1, hf = r & 1;
            const float rc = rowc[r];
            float s = 0.f;
            #pragma unroll
            for (int j = 0; j < 4; j++) {
                #pragma unroll
                for (int q = 0; q < 2; q++) {
                    float cc = q ? ct2[j].y : ct2[j].x;
                    float t  = fmaf(acc[i][j][hf * 2 + q], inv4, cc);
                    float v  = __fadd_rn(t, rc);
                    v = fmaxf(v, -170.f);          // no int32 wrap possible
                    float rr = __fadd_rn(v, MAGICF);
                    float kf = __fadd_rn(rr, -MAGICF);
                    float f  = __fadd_rn(v, -kf);
                    float p  = fmaf(f, fmaf(f, 0.24263113f, 0.70360518f), 0.99992640f);
                    int eb = __float_as_int(p) + (__float_as_int(rr) << 23);
                    eb = max(eb, 0);
                    s += __int_as_float(eb);
                }
            }
            sum[r] += s;
        }
        __syncthreads();
    }

    // ---- reduce: quad -> warp-col -> CTA ----
    #pragma unroll
    for (int r = 0; r < 4; r++) {
        sum[r] += __shfl_xor_sync(0xffffffffu, sum[r], 1);
        sum[r] += __shfl_xor_sync(0xffffffffu, sum[r], 2);
    }
    if (c == 0) {
        #pragma unroll
        for (int r = 0; r < 4; r++) {
            int rl = wm * 32 + (r >> 1) * 16 + (r & 1) * 8 + g;
            red[wn][rl] = sum[r];
        }
    }
    __syncthreads();
    if (tid < MT) {
        float tot = red[0][tid] + red[1][tid] + red[2][tid] + red[3][tid];
        g_part[split * MM + m0 + tid] = tot;
    }
    __syncthreads();

    // ---- tail CTA per m-block merges the 23 split sums ----
    if (tid == 0) {
        __threadfence();
        int old = atomicAdd(&g_cnt[blockIdx.x], 1);
        sdone = (old == NSPLIT - 1) ? 1 : 0;
        if (sdone) __threadfence();
    }
    __syncthreads();
    if (sdone) {
        if (tid < MT) {
            float tot = 0.f;
            #pragma unroll
            for (int s = 0; s < NSPLIT; s++) tot += __ldcg(&g_part[s * MM + m0 + tid]);
            // coeff = -ln(50000) - 32*ln(2*pi)
            out[m0 + tid] = -69.63184443f
                          + (log2f(tot) - 38.f) * 0.6931471805599453f;
        }
        __syncthreads();
        if (tid == 0) g_cnt[blockIdx.x] = 0;   // reset for next graph replay
    }
}

extern "C" void kernel_launch(void* const* d_in, const int* in_sizes, int n_in,
                              void* d_out, int out_size) {
    const float* x  = (const float*)d_in[0];   // [4096, 64]
    const float* X  = (const float*)d_in[1];   // [50000, 64]
    const float* bw = (const float*)d_in[2];   // [1]

    prep_all<<<NPAD / 32 + MM / 32, 256>>>(x, X, bw);   // 1696 blocks

    dim3 grid(MM / MT, NSPLIT);                         // (64, 23)
    kde_main<<<grid, 256>>>(bw, (float*)d_out);
}

// round 4
// speedup vs baseline: 1.5656x; 1.2001x over previous
#include <cuda_runtime.h>
#include <cuda_bf16.h>
#include <cstdint>

// GaussianKernelDensity: out[m] = coeff + logsumexp_n( -||x_m - X_n||^2 / (2 b^2) )
// M=4096, N=50000, D=64.
//  Launch 1: prep_all — pack x,X to bf16; fold norms+bandwidth into per-row/col
//            base-2 constants (colc = -|X|^2*inv2, rowc = -|x|^2*inv2 + 38).
//  Launch 2: kde_main — bf16 HMMA with A-fragments in registers, B via ldmatrix
//            from cp.async double-buffered smem, PACKED f32x2 exp2 epilogue
//            (2 elements per issue slot; int-domain exponent clamp k >= -124 so
//            the splice needs one IMNMX + one LEA per element), per-split row
//            sums, tail-CTA merge writes out.

#define MM 4096
#define NN 50000
#define DD 64
#define NPAD 50176
#define NSPLIT 23
#define CHUNK 2176              // 17 * 128
#define NTILES 17
#define MT 64
#define NT 128
#define MAGICF 12582912.0f      // 1.5 * 2^23
#define CLAMPI 0x4B3FFF84       // bits(MAGICF) - 124  -> k >= -124, eb always > 0

// device scratch
__device__ __nv_bfloat16 g_Xb[NPAD * DD];
__device__ float         g_CT[NPAD];       // -|X_n|^2 * inv2  (pad rows: -1000)
__device__ __nv_bfloat16 g_xb[MM * DD];
__device__ float         g_RT[MM];         // -|x_m|^2 * inv2 + 38
__device__ float         g_part[NSPLIT * MM];
__device__ int           g_cnt[MM / MT];

#define LDSM4(r0, r1, r2, r3, addr)                                              \
    asm volatile("ldmatrix.sync.aligned.m8n8.x4.shared.b16 {%0,%1,%2,%3}, [%4];" \
                 : "=r"(r0), "=r"(r1), "=r"(r2), "=r"(r3) : "r"(addr))

__device__ __forceinline__ void cp16(uint32_t dst, const void* src) {
    asm volatile("cp.async.cg.shared.global [%0], [%1], 16;" :: "r"(dst), "l"(src));
}
__device__ __forceinline__ uint32_t smem_u32(const void* p) {
    return (uint32_t)__cvta_generic_to_shared(p);
}

// ---- packed f32x2 helpers (Blackwell) ----
__device__ __forceinline__ uint64_t pk2(float lo, float hi) {
    uint64_t r;
    asm("mov.b64 %0, {%1, %2};" : "=l"(r) : "f"(lo), "f"(hi));
    return r;
}
__device__ __forceinline__ void upk2(uint32_t& lo, uint32_t& hi, uint64_t v) {
    asm("mov.b64 {%0, %1}, %2;" : "=r"(lo), "=r"(hi) : "l"(v));
}
__device__ __forceinline__ uint64_t fma2(uint64_t a, uint64_t b, uint64_t c) {
    uint64_t d;
    asm("fma.rn.f32x2 %0, %1, %2, %3;" : "=l"(d) : "l"(a), "l"(b), "l"(c));
    return d;
}
__device__ __forceinline__ uint64_t add2(uint64_t a, uint64_t b) {
    uint64_t d;
    asm("add.rn.f32x2 %0, %1, %2;" : "=l"(d) : "l"(a), "l"(b));
    return d;
}

// ---------------- prep: pack + fold constants ----------------
__global__ void prep_all(const float* __restrict__ xin,
                         const float* __restrict__ Xin,
                         const float* __restrict__ bw) {
    const float b = bw[0];
    const float inv2 = 1.4426950408889634f / (2.f * b * b);   // log2e / (2 b^2)
    const int blk = blockIdx.x, tid = threadIdx.x;
    const int l8 = tid & 7;

    if (blk < NPAD / 32) {                       // X rows (incl. pad)
        int row = blk * 32 + (tid >> 3);
        uint4 packed = make_uint4(0u, 0u, 0u, 0u);
        __nv_bfloat16* hp = reinterpret_cast<__nv_bfloat16*>(&packed);
        float ss = 0.f;
        if (row < NN) {
            const float4* s4 = reinterpret_cast<const float4*>(Xin + row * DD + l8 * 8);
            float4 a = s4[0], d = s4[1];
            ss = a.x*a.x + a.y*a.y + a.z*a.z + a.w*a.w
               + d.x*d.x + d.y*d.y + d.z*d.z + d.w*d.w;
            hp[0] = __float2bfloat16_rn(a.x); hp[1] = __float2bfloat16_rn(a.y);
            hp[2] = __float2bfloat16_rn(a.z); hp[3] = __float2bfloat16_rn(a.w);
            hp[4] = __float2bfloat16_rn(d.x); hp[5] = __float2bfloat16_rn(d.y);
            hp[6] = __float2bfloat16_rn(d.z); hp[7] = __float2bfloat16_rn(d.w);
        }
        *reinterpret_cast<uint4*>(&g_Xb[row * DD + l8 * 8]) = packed;
        ss += __shfl_xor_sync(0xffffffffu, ss, 1);
        ss += __shfl_xor_sync(0xffffffffu, ss, 2);
        ss += __shfl_xor_sync(0xffffffffu, ss, 4);
        if (l8 == 0) g_CT[row] = (row < NN) ? (-ss * inv2) : -1000.f;
    } else {                                     // x rows
        int row = (blk - NPAD / 32) * 32 + (tid >> 3);
        const float4* s4 = reinterpret_cast<const float4*>(xin + row * DD + l8 * 8);
        float4 a = s4[0], d = s4[1];
        float ss = a.x*a.x + a.y*a.y + a.z*a.z + a.w*a.w
                 + d.x*d.x + d.y*d.y + d.z*d.z + d.w*d.w;
        uint4 packed;
        __nv_bfloat16* hp = reinterpret_cast<__nv_bfloat16*>(&packed);
        hp[0] = __float2bfloat16_rn(a.x); hp[1] = __float2bfloat16_rn(a.y);
        hp[2] = __float2bfloat16_rn(a.z); hp[3] = __float2bfloat16_rn(a.w);
        hp[4] = __float2bfloat16_rn(d.x); hp[5] = __float2bfloat16_rn(d.y);
        hp[6] = __float2bfloat16_rn(d.z); hp[7] = __float2bfloat16_rn(d.w);
        *reinterpret_cast<uint4*>(&g_xb[row * DD + l8 * 8]) = packed;
        ss += __shfl_xor_sync(0xffffffffu, ss, 1);
        ss += __shfl_xor_sync(0xffffffffu, ss, 2);
        ss += __shfl_xor_sync(0xffffffffu, ss, 4);
        if (l8 == 0) g_RT[row] = -ss * inv2 + 38.f;
    }
}

// ---------------- main: GEMM + packed exp2 sum ----------------
__global__ __launch_bounds__(256, 2) void kde_main(const float* __restrict__ bw,
                                                   float* __restrict__ out) {
    __shared__ __nv_bfloat16 xs[MT][72];          //  9216 B
    __shared__ __nv_bfloat16 Xd[2][NT][72];       // 36864 B
    __shared__ float ctile[2][NT];                //  1024 B
    __shared__ float red[4][MT];                  //  1024 B
    __shared__ int sdone;

    const int tid  = threadIdx.x;
    const int warp = tid >> 5;
    const int lane = tid & 31;
    const int g = lane >> 2;
    const int c = lane & 3;
    const int wm = warp >> 2;     // 0..1 (M)
    const int wn = warp & 3;      // 0..3 (N)

    const float b    = bw[0];
    const float inv4 = 1.4426950408889634f / (b * b);   // log2e / b^2

    const int m0    = blockIdx.x * MT;
    const int split = blockIdx.y;
    const int n0    = split * CHUNK;

    // ---- hoisted cp.async source pointers / smem destinations ----
    const __nv_bfloat16* gsrc[4];
    uint32_t sdst0[4];
    #pragma unroll
    for (int k = 0; k < 4; k++) {
        int idx = tid + k * 256; int row = idx >> 3, ch = idx & 7;
        gsrc[k]  = g_Xb + (n0 + row) * DD + ch * 8;
        sdst0[k] = smem_u32(&Xd[0][row][ch * 8]);
    }
    const uint32_t stagesz = (uint32_t)sizeof(Xd[0]);
    const float* gct = g_CT + n0 + (tid & 31) * 4;
    const uint32_t cdst0 = smem_u32(&ctile[0][(tid & 31) * 4]);

    // ---- x tile -> smem ----
    {
        int row = tid >> 2, q = tid & 3;
        const uint4* s = reinterpret_cast<const uint4*>(g_xb + (m0 + row) * DD + q * 16);
        uint4 v0 = s[0], v1 = s[1];
        *reinterpret_cast<uint4*>(&xs[row][q * 16])     = v0;
        *reinterpret_cast<uint4*>(&xs[row][q * 16 + 8]) = v1;
    }

    // ---- prefetch tile 0 ----
    #pragma unroll
    for (int k = 0; k < 4; k++) cp16(sdst0[k], gsrc[k]);
    if (tid < 32) cp16(cdst0, gct);
    asm volatile("cp.async.commit_group;");
    __syncthreads();    // xs ready

    // ---- A fragments for the whole CTA lifetime ----
    const int lr = (lane & 7) + ((lane >> 3) & 1) * 8;
    const int lc = (lane >> 4) * 8;
    uint32_t afr[4][8];
    #pragma unroll
    for (int ks = 0; ks < 4; ks++)
        #pragma unroll
        for (int i = 0; i < 2; i++) {
            uint32_t a0, a1, a2, a3;
            uint32_t addr = smem_u32(&xs[wm * 32 + i * 16 + lr][ks * 16 + lc]);
            LDSM4(a0, a1, a2, a3, addr);
            afr[ks][i * 4 + 0] = a0; afr[ks][i * 4 + 1] = a1;
            afr[ks][i * 4 + 2] = a2; afr[ks][i * 4 + 3] = a3;
        }

    // packed per-row constants and packed epilogue constants
    uint64_t rc2[4];
    #pragma unroll
    for (int r = 0; r < 4; r++) {
        int rl = wm * 32 + (r >> 1) * 16 + (r & 1) * 8 + g;
        float rv = g_RT[m0 + rl];
        rc2[r] = pk2(rv, rv);
    }
    const uint64_t inv42  = pk2(inv4, inv4);
    const uint64_t magic2 = pk2(MAGICF, MAGICF);
    const uint64_t nmagic2= pk2(-MAGICF, -MAGICF);
    const uint64_t none2  = pk2(-1.f, -1.f);
    const uint64_t cP2    = pk2(0.24263113f, 0.24263113f);
    const uint64_t cP1    = pk2(0.70360518f, 0.70360518f);
    const uint64_t cP0    = pk2(0.99992640f, 0.99992640f);

    uint64_t s2[4];
    #pragma unroll
    for (int r = 0; r < 4; r++) s2[r] = 0ull;

    for (int it = 0; it < NTILES; it++) {
        const int st = it & 1;
        if (it + 1 < NTILES) {
            #pragma unroll
            for (int k = 0; k < 4; k++) {
                gsrc[k] += NT * DD;
                cp16(sdst0[k] + (st ^ 1) * stagesz, gsrc[k]);
            }
            if (tid < 32) cp16(cdst0 + (st ^ 1) * (uint32_t)sizeof(ctile[0]),
                               gct + (it + 1) * NT);
            asm volatile("cp.async.commit_group;");
            asm volatile("cp.async.wait_group 1;");
        } else {
            asm volatile("cp.async.wait_group 0;");
        }
        __syncthreads();

        uint64_t cc2[4];
        #pragma unroll
        for (int j = 0; j < 4; j++) {
            float2 cf = *reinterpret_cast<const float2*>(&ctile[st][wn * 32 + j * 8 + 2 * c]);
            cc2[j] = pk2(cf.x, cf.y);
        }

        float acc[2][4][4];
        #pragma unroll
        for (int i = 0; i < 2; i++)
            #pragma unroll
            for (int j = 0; j < 4; j++)
                #pragma unroll
                for (int q = 0; q < 4; q++) acc[i][j][q] = 0.f;

        #pragma unroll
        for (int ks = 0; ks < 4; ks++) {
            uint32_t bfr[2][4];
            #pragma unroll
            for (int jj = 0; jj < 2; jj++) {
                uint32_t addr = smem_u32(&Xd[st][wn * 32 + jj * 16 + lr][ks * 16 + lc]);
                LDSM4(bfr[jj][0], bfr[jj][1], bfr[jj][2], bfr[jj][3], addr);
            }
            #pragma unroll
            for (int i = 0; i < 2; i++)
                #pragma unroll
                for (int j = 0; j < 4; j++) {
                    const int jj = j >> 1, od = j & 1;
                    asm volatile(
                        "mma.sync.aligned.m16n8k16.row.col.f32.bf16.bf16.f32 "
                        "{%0,%1,%2,%3}, {%4,%5,%6,%7}, {%8,%9}, {%0,%1,%2,%3};"
                        : "+f"(acc[i][j][0]), "+f"(acc[i][j][1]),
                          "+f"(acc[i][j][2]), "+f"(acc[i][j][3])
                        : "r"(afr[ks][i * 4 + 0]), "r"(afr[ks][i * 4 + 1]),
                          "r"(afr[ks][i * 4 + 2]), "r"(afr[ks][i * 4 + 3]),
                          "r"(bfr[jj][od]), "r"(bfr[jj][2 + od]));
                }
        }

        // packed epilogue: e = 2^v per lane-pair; v = acc*inv4 + cc + rc.
        // exp2: rr = rn(v+magic); f = v-(rr-magic); p = poly(f);
        // exponent splice in int with k clamped >= -124 (eb always > 0).
        #pragma unroll
        for (int r = 0; r < 4; r++) {
            const int i = r >> 1, hf = r & 1;
            #pragma unroll
            for (int j = 0; j < 4; j++) {
                uint64_t ccr = add2(cc2[j], rc2[r]);
                uint64_t a2  = pk2(acc[i][j][hf * 2], acc[i][j][hf * 2 + 1]);
                uint64_t v2  = fma2(a2, inv42, ccr);
                uint64_t rr2 = add2(v2, magic2);
                uint64_t kf2 = add2(rr2, nmagic2);
                uint64_t f2  = fma2(kf2, none2, v2);
                uint64_t q2  = fma2(f2, cP2, cP1);
                uint64_t p2  = fma2(f2, q2, cP0);
                uint32_t rlo, rhi, plo, phi;
                upk2(rlo, rhi, rr2);
                upk2(plo, phi, p2);
                int elo = (int)plo + (max((int)rlo, (int)CLAMPI) << 23);
                int ehi = (int)phi + (max((int)rhi, (int)CLAMPI) << 23);
                s2[r] = add2(s2[r], pk2(__int_as_float(elo), __int_as_float(ehi)));
            }
        }
        __syncthreads();
    }

    // ---- reduce: pair -> quad -> warp-col -> CTA ----
    float sum[4];
    #pragma unroll
    for (int r = 0; r < 4; r++) {
        uint32_t lo, hi;
        upk2(lo, hi, s2[r]);
        sum[r] = __uint_as_float(lo) + __uint_as_float(hi);
        sum[r] += __shfl_xor_sync(0xffffffffu, sum[r], 1);
        sum[r] += __shfl_xor_sync(0xffffffffu, sum[r], 2);
    }
    if (c == 0) {
        #pragma unroll
        for (int r = 0; r < 4; r++) {
            int rl = wm * 32 + (r >> 1) * 16 + (r & 1) * 8 + g;
            red[wn][rl] = sum[r];
        }
    }
    __syncthreads();
    if (tid < MT) {
        float tot = red[0][tid] + red[1][tid] + red[2][tid] + red[3][tid];
        g_part[split * MM + m0 + tid] = tot;
    }
    __syncthreads();

    // ---- tail CTA per m-block merges the 23 split sums ----
    if (tid == 0) {
        __threadfence();
        int old = atomicAdd(&g_cnt[blockIdx.x], 1);
        sdone = (old == NSPLIT - 1) ? 1 : 0;
        if (sdone) __threadfence();
    }
    __syncthreads();
    if (sdone) {
        if (tid < MT) {
            float tot = 0.f;
            #pragma unroll
            for (int s = 0; s < NSPLIT; s++) tot += __ldcg(&g_part[s * MM + m0 + tid]);
            // coeff = -ln(50000) - 32*ln(2*pi)
            out[m0 + tid] = -69.63184443f
                          + (log2f(tot) - 38.f) * 0.6931471805599453f;
        }
        __syncthreads();
        if (tid == 0) g_cnt[blockIdx.x] = 0;   // reset for next graph replay
    }
}

extern "C" void kernel_launch(void* const* d_in, const int* in_sizes, int n_in,
                              void* d_out, int out_size) {
    const float* x  = (const float*)d_in[0];   // [4096, 64]
    const float* X  = (const float*)d_in[1];   // [50000, 64]
    const float* bw = (const float*)d_in[2];   // [1]

    prep_all<<<NPAD / 32 + MM / 32, 256>>>(x, X, bw);   // 1696 blocks

    dim3 grid(MM / MT, NSPLIT);                         // (64, 23)
    kde_main<<<grid, 256>>>(bw, (float*)d_out);
}

// round 6
// speedup vs baseline: 1.5802x; 1.0093x over previous
#include <cuda_runtime.h>
#include <cuda_bf16.h>
#include <cstdint>

// GaussianKernelDensity: out[m] = coeff + logsumexp_n( -||x_m - X_n||^2 / (2 b^2) )
// M=4096, N=50000, D=64.
//  Launch 1: prep_all — pack x,X to bf16; fold norms+bandwidth into per-row/col
//            base-2 constants.
//  Launch 2: kde_main — bf16 HMMA with A-fragments in registers, B via ldmatrix
//            from a 3-STAGE cp.async pipeline (ONE __syncthreads per tile).
//            Static smem = exactly 48KB: 3 stages x 128 rows x 128B, SW128
//            swizzled (no padding); x-tile aliases stage 2; column constants
//            live in registers (L2 __ldg, prefetched one tile ahead); the
//            final reduction aliases stage 0. Packed f32x2 exp2 epilogue,
//            per-split row sums, tail-CTA merge.

#define MM 4096
#define NN 50000
#define DD 64
#define NPAD 50176
#define NSPLIT 23
#define CHUNK 2176              // 17 * 128
#define NTILES 17
#define MT 64
#define NT 128
#define STAGE 16384             // 128 rows * 128 B
#define MAGICF 12582912.0f      // 1.5 * 2^23
#define CLAMPI 0x4B3FFF84       // bits(MAGICF) - 124  -> k >= -124, eb always > 0

// device scratch
__device__ __nv_bfloat16 g_Xb[NPAD * DD];
__device__ float         g_CT[NPAD];       // -|X_n|^2 * inv2  (pad rows: -1000)
__device__ __nv_bfloat16 g_xb[MM * DD];
__device__ float         g_RT[MM];         // -|x_m|^2 * inv2 + 38
__device__ float         g_part[NSPLIT * MM];
__device__ int           g_cnt[MM / MT];

#define LDSM4(r0, r1, r2, r3, addr)                                              \
    asm volatile("ldmatrix.sync.aligned.m8n8.x4.shared.b16 {%0,%1,%2,%3}, [%4];" \
                 : "=r"(r0), "=r"(r1), "=r"(r2), "=r"(r3) : "r"(addr))

__device__ __forceinline__ void cp16(uint32_t dst, const void* src) {
    asm volatile("cp.async.cg.shared.global [%0], [%1], 16;" :: "r"(dst), "l"(src));
}
__device__ __forceinline__ uint32_t smem_u32(const void* p) {
    return (uint32_t)__cvta_generic_to_shared(p);
}

// ---- packed f32x2 helpers (Blackwell) ----
__device__ __forceinline__ uint64_t pk2(float lo, float hi) {
    uint64_t r;
    asm("mov.b64 %0, {%1, %2};" : "=l"(r) : "f"(lo), "f"(hi));
    return r;
}
__device__ __forceinline__ void upk2(uint32_t& lo, uint32_t& hi, uint64_t v) {
    asm("mov.b64 {%0, %1}, %2;" : "=r"(lo), "=r"(hi) : "l"(v));
}
__device__ __forceinline__ uint64_t fma2(uint64_t a, uint64_t b, uint64_t c) {
    uint64_t d;
    asm("fma.rn.f32x2 %0, %1, %2, %3;" : "=l"(d) : "l"(a), "l"(b), "l"(c));
    return d;
}
__device__ __forceinline__ uint64_t add2(uint64_t a, uint64_t b) {
    uint64_t d;
    asm("add.rn.f32x2 %0, %1, %2;" : "=l"(d) : "l"(a), "l"(b));
    return d;
}

// ---------------- prep: pack + fold constants ----------------
__global__ void prep_all(const float* __restrict__ xin,
                         const float* __restrict__ Xin,
                         const float* __restrict__ bw) {
    const float b = bw[0];
    const float inv2 = 1.4426950408889634f / (2.f * b * b);   // log2e / (2 b^2)
    const int blk = blockIdx.x, tid = threadIdx.x;
    const int l8 = tid & 7;

    if (blk < NPAD / 32) {                       // X rows (incl. pad)
        int row = blk * 32 + (tid >> 3);
        uint4 packed = make_uint4(0u, 0u, 0u, 0u);
        __nv_bfloat16* hp = reinterpret_cast<__nv_bfloat16*>(&packed);
        float ss = 0.f;
        if (row < NN) {
            const float4* s4 = reinterpret_cast<const float4*>(Xin + row * DD + l8 * 8);
            float4 a = s4[0], d = s4[1];
            ss = a.x*a.x + a.y*a.y + a.z*a.z + a.w*a.w
               + d.x*d.x + d.y*d.y + d.z*d.z + d.w*d.w;
            hp[0] = __float2bfloat16_rn(a.x); hp[1] = __float2bfloat16_rn(a.y);
            hp[2] = __float2bfloat16_rn(a.z); hp[3] = __float2bfloat16_rn(a.w);
            hp[4] = __float2bfloat16_rn(d.x); hp[5] = __float2bfloat16_rn(d.y);
            hp[6] = __float2bfloat16_rn(d.z); hp[7] = __float2bfloat16_rn(d.w);
        }
        *reinterpret_cast<uint4*>(&g_Xb[row * DD + l8 * 8]) = packed;
        ss += __shfl_xor_sync(0xffffffffu, ss, 1);
        ss += __shfl_xor_sync(0xffffffffu, ss, 2);
        ss += __shfl_xor_sync(0xffffffffu, ss, 4);
        if (l8 == 0) g_CT[row] = (row < NN) ? (-ss * inv2) : -1000.f;
    } else {                                     // x rows
        int row = (blk - NPAD / 32) * 32 + (tid >> 3);
        const float4* s4 = reinterpret_cast<const float4*>(xin + row * DD + l8 * 8);
        float4 a = s4[0], d = s4[1];
        float ss = a.x*a.x + a.y*a.y + a.z*a.z + a.w*a.w
                 + d.x*d.x + d.y*d.y + d.z*d.z + d.w*d.w;
        uint4 packed;
        __nv_bfloat16* hp = reinterpret_cast<__nv_bfloat16*>(&packed);
        hp[0] = __float2bfloat16_rn(a.x); hp[1] = __float2bfloat16_rn(a.y);
        hp[2] = __float2bfloat16_rn(a.z); hp[3] = __float2bfloat16_rn(a.w);
        hp[4] = __float2bfloat16_rn(d.x); hp[5] = __float2bfloat16_rn(d.y);
        hp[6] = __float2bfloat16_rn(d.z); hp[7] = __float2bfloat16_rn(d.w);
        *reinterpret_cast<uint4*>(&g_xb[row * DD + l8 * 8]) = packed;
        ss += __shfl_xor_sync(0xffffffffu, ss, 1);
        ss += __shfl_xor_sync(0xffffffffu, ss, 2);
        ss += __shfl_xor_sync(0xffffffffu, ss, 4);
        if (l8 == 0) g_RT[row] = -ss * inv2 + 38.f;
    }
}

// ---------------- main: GEMM + packed exp2 sum ----------------
__global__ __launch_bounds__(256, 2) void kde_main(const float* __restrict__ bw,
                                                   float* __restrict__ out) {
    // Entire static smem: 3 SW128-swizzled B stages (48KB exactly).
    // Stage 2 doubles as the x-tile before tile 2 is prefetched; stage 0
    // doubles as the reduction buffer after the main loop.
    __shared__ __align__(1024) char S[3 * STAGE];

    const int tid  = threadIdx.x;
    const int warp = tid >> 5;
    const int lane = tid & 31;
    const int g = lane >> 2;
    const int c = lane & 3;
    const int wm = warp >> 2;     // 0..1 (M)
    const int wn = warp & 3;      // 0..3 (N)

    const float b    = bw[0];
    const float inv4 = 1.4426950408889634f / (b * b);   // log2e / b^2

    const int m0    = blockIdx.x * MT;
    const int split = blockIdx.y;
    const int n0    = split * CHUNK;

    const uint32_t Sb = smem_u32(S);

    // ---- hoisted cp.async source pointers / swizzled smem destinations ----
    const __nv_bfloat16* gsrc[4];
    uint32_t sdst0[4];
    #pragma unroll
    for (int k = 0; k < 4; k++) {
        int idx = tid + k * 256; int row = idx >> 3, ch = idx & 7;
        gsrc[k]  = g_Xb + (n0 + row) * DD + ch * 8;
        sdst0[k] = Sb + row * 128 + ((ch ^ (row & 7)) * 16);
    }

    // ---- prefetch tiles 0 and 1 (two committed groups) ----
    #pragma unroll
    for (int k = 0; k < 4; k++) cp16(sdst0[k], gsrc[k]);
    asm volatile("cp.async.commit_group;");
    #pragma unroll
    for (int k = 0; k < 4; k++) { gsrc[k] += NT * DD; cp16(sdst0[k] + STAGE, gsrc[k]); }
    asm volatile("cp.async.commit_group;");

    // ---- x tile -> stage 2 (swizzled; consumed before tile 2 arrives) ----
    {
        int row = tid >> 2, q = tid & 3;
        const uint4* s = reinterpret_cast<const uint4*>(g_xb + (m0 + row) * DD + q * 16);
        uint4 v0 = s[0], v1 = s[1];
        int base = 2 * STAGE + row * 128;
        int msk = row & 7;
        *reinterpret_cast<uint4*>(S + base + (((2 * q)     ^ msk) * 16)) = v0;
        *reinterpret_cast<uint4*>(S + base + (((2 * q + 1) ^ msk) * 16)) = v1;
    }
    __syncthreads();    // x tile visible

    // ---- A fragments for the whole CTA lifetime ----
    const int lr = (lane & 7) + ((lane >> 3) & 1) * 8;
    const int cb = lane >> 4;                    // chunk low bit (0/1)
    uint32_t afr[4][8];
    #pragma unroll
    for (int i = 0; i < 2; i++) {
        int rowp = wm * 32 + i * 16 + lr;
        uint32_t rb = Sb + 2 * STAGE + rowp * 128;
        int rm = rowp & 7;
        #pragma unroll
        for (int ks = 0; ks < 4; ks++) {
            uint32_t a0, a1, a2, a3;
            LDSM4(a0, a1, a2, a3, rb + (((ks * 2 + cb) ^ rm) * 16));
            afr[ks][i * 4 + 0] = a0; afr[ks][i * 4 + 1] = a1;
            afr[ks][i * 4 + 2] = a2; afr[ks][i * 4 + 3] = a3;
        }
    }

    // B ldmatrix row bases (per warp, fixed across tiles)
    uint32_t rB_off[2]; int rB_msk[2];
    #pragma unroll
    for (int jj = 0; jj < 2; jj++) {
        int rowp = wn * 32 + jj * 16 + lr;
        rB_off[jj] = (uint32_t)(rowp * 128);
        rB_msk[jj] = rowp & 7;
    }

    // packed per-row constants and packed epilogue constants
    uint64_t rc2[4];
    #pragma unroll
    for (int r = 0; r < 4; r++) {
        int rl = wm * 32 + (r >> 1) * 16 + (r & 1) * 8 + g;
        float rv = g_RT[m0 + rl];
        rc2[r] = pk2(rv, rv);
    }
    const uint64_t inv42  = pk2(inv4, inv4);
    const uint64_t magic2 = pk2(MAGICF, MAGICF);
    const uint64_t nmagic2= pk2(-MAGICF, -MAGICF);
    const uint64_t none2  = pk2(-1.f, -1.f);
    const uint64_t cP2    = pk2(0.24263113f, 0.24263113f);
    const uint64_t cP1    = pk2(0.70360518f, 0.70360518f);
    const uint64_t cP0    = pk2(0.99992640f, 0.99992640f);

    // column constants: register prefetch, one tile ahead (L2-resident)
    const float* gc = g_CT + n0 + wn * 32 + 2 * c;
    float2 cv[4];
    #pragma unroll
    for (int j = 0; j < 4; j++) cv[j] = __ldg((const float2*)(gc + j * 8));

    uint64_t s2[4];
    #pragma unroll
    for (int r = 0; r < 4; r++) s2[r] = 0ull;

    int bufw = 2;   // stage for prefetch of tile it+2
    int st   = 0;   // stage for tile it

    for (int it = 0; it < NTILES; it++) {
        // wait own tile-it group, one barrier: cross-thread visibility of tile
        // it AND all warps done reading tile it-1 (so stage (it+2)%3 is free).
        if (it < NTILES - 1) {
            asm volatile("cp.async.wait_group 1;");
        } else {
            asm volatile("cp.async.wait_group 0;");
        }
        __syncthreads();

        if (it + 2 < NTILES) {
            #pragma unroll
            for (int k = 0; k < 4; k++) {
                gsrc[k] += NT * DD;
                cp16(sdst0[k] + (uint32_t)bufw * STAGE, gsrc[k]);
            }
            asm volatile("cp.async.commit_group;");
            bufw = (bufw == 2) ? 0 : bufw + 1;
        }

        // combine col consts (tile it) with row consts; then prefetch tile it+1
        uint64_t ccr[4][4];
        #pragma unroll
        for (int j = 0; j < 4; j++) {
            uint64_t cc2 = pk2(cv[j].x, cv[j].y);
            #pragma unroll
            for (int r = 0; r < 4; r++) ccr[r][j] = add2(cc2, rc2[r]);
        }
        #pragma unroll
        for (int j = 0; j < 4; j++)
            cv[j] = __ldg((const float2*)(gc + (it + 1) * NT + j * 8));

        float acc[2][4][4];
        #pragma unroll
        for (int i = 0; i < 2; i++)
            #pragma unroll
            for (int j = 0; j < 4; j++)
                #pragma unroll
                for (int q = 0; q < 4; q++) acc[i][j][q] = 0.f;

        const uint32_t stb = Sb + (uint32_t)st * STAGE;
        #pragma unroll
        for (int ks = 0; ks < 4; ks++) {
            uint32_t bfr[2][4];
            #pragma unroll
            for (int jj = 0; jj < 2; jj++) {
                uint32_t addr = stb + rB_off[jj] + (((ks * 2 + cb) ^ rB_msk[jj]) * 16);
                LDSM4(bfr[jj][0], bfr[jj][1], bfr[jj][2], bfr[jj][3], addr);
            }
            #pragma unroll
            for (int i = 0; i < 2; i++)
                #pragma unroll
                for (int j = 0; j < 4; j++) {
                    const int jj = j >> 1, od = j & 1;
                    asm volatile(
                        "mma.sync.aligned.m16n8k16.row.col.f32.bf16.bf16.f32 "
                        "{%0,%1,%2,%3}, {%4,%5,%6,%7}, {%8,%9}, {%0,%1,%2,%3};"
                        : "+f"(acc[i][j][0]), "+f"(acc[i][j][1]),
                          "+f"(acc[i][j][2]), "+f"(acc[i][j][3])
                        : "r"(afr[ks][i * 4 + 0]), "r"(afr[ks][i * 4 + 1]),
                          "r"(afr[ks][i * 4 + 2]), "r"(afr[ks][i * 4 + 3]),
                          "r"(bfr[jj][od]), "r"(bfr[jj][2 + od]));
                }
        }

        // packed epilogue: e = 2^v per lane-pair; v = acc*inv4 + ccr.
        #pragma unroll
        for (int r = 0; r < 4; r++) {
            const int i = r >> 1, hf = r & 1;
            #pragma unroll
            for (int j = 0; j < 4; j++) {
                uint64_t a2  = pk2(acc[i][j][hf * 2], acc[i][j][hf * 2 + 1]);
                uint64_t v2  = fma2(a2, inv42, ccr[r][j]);
                uint64_t rr2 = add2(v2, magic2);
                uint64_t kf2 = add2(rr2, nmagic2);
                uint64_t f2  = fma2(kf2, none2, v2);
                uint64_t q2  = fma2(f2, cP2, cP1);
                uint64_t p2  = fma2(f2, q2, cP0);
                uint32_t rlo, rhi, plo, phi;
                upk2(rlo, rhi, rr2);
                upk2(plo, phi, p2);
                int elo = (int)plo + (max((int)rlo, (int)CLAMPI) << 23);
                int ehi = (int)phi + (max((int)rhi, (int)CLAMPI) << 23);
                s2[r] = add2(s2[r], pk2(__int_as_float(elo), __int_as_float(ehi)));
            }
        }

        st = (st == 2) ? 0 : st + 1;
    }

    // ---- reduce: pair -> quad -> warp-col -> CTA (red aliases stage 0) ----
    float* redp = reinterpret_cast<float*>(S);            // [4][MT]
    int*   sdonep = reinterpret_cast<int*>(S + 4 * MT * 4);

    float sum[4];
    #pragma unroll
    for (int r = 0; r < 4; r++) {
        uint32_t lo, hi;
        upk2(lo, hi, s2[r]);
        sum[r] = __uint_as_float(lo) + __uint_as_float(hi);
        sum[r] += __shfl_xor_sync(0xffffffffu, sum[r], 1);
        sum[r] += __shfl_xor_sync(0xffffffffu, sum[r], 2);
    }
    __syncthreads();   // all warps done with B stages; stage 0 reusable
    if (c == 0) {
        #pragma unroll
        for (int r = 0; r < 4; r++) {
            int rl = wm * 32 + (r >> 1) * 16 + (r & 1) * 8 + g;
            redp[wn * MT + rl] = sum[r];
        }
    }
    __syncthreads();
    if (tid < MT) {
        float tot = redp[tid] + redp[MT + tid] + redp[2 * MT + tid] + redp[3 * MT + tid];
        g_part[split * MM + m0 + tid] = tot;
    }
    __syncthreads();

    // ---- tail CTA per m-block merges the 23 split sums ----
    if (tid == 0) {
        __threadfence();
        int old = atomicAdd(&g_cnt[blockIdx.x], 1);
        sdonep[0] = (old == NSPLIT - 1) ? 1 : 0;
        if (sdonep[0]) __threadfence();
    }
    __syncthreads();
    if (sdonep[0]) {
        if (tid < MT) {
            float tot = 0.f;
            #pragma unroll
            for (int s = 0; s < NSPLIT; s++) tot += __ldcg(&g_part[s * MM + m0 + tid]);
            // coeff = -ln(50000) - 32*ln(2*pi)
            out[m0 + tid] = -69.63184443f
                          + (log2f(tot) - 38.f) * 0.6931471805599453f;
        }
        __syncthreads();
        if (tid == 0) g_cnt[blockIdx.x] = 0;   // reset for next graph replay
    }
}

extern "C" void kernel_launch(void* const* d_in, const int* in_sizes, int n_in,
                              void* d_out, int out_size) {
    const float* x  = (const float*)d_in[0];   // [4096, 64]
    const float* X  = (const float*)d_in[1];   // [50000, 64]
    const float* bw = (const float*)d_in[2];   // [1]

    prep_all<<<NPAD / 32 + MM / 32, 256>>>(x, X, bw);   // 1696 blocks

    dim3 grid(MM / MT, NSPLIT);                         // (64, 23)
    kde_main<<<grid, 256>>>(bw, (float*)d_out);
}